// round 1
// baseline (speedup 1.0000x reference)
#include <cuda_runtime.h>
#include <math.h>

// Problem constants (fixed by the dataset)
#define NNODES 100000
#define HDIM   128
#define NGRAPH 256
#define MTILE  64

// ---------------- scratch (device globals: allocation-free) ----------------
__device__ float g_bufA[NNODES * HDIM];
__device__ float g_bufB[NNODES * HDIM];
__device__ float g_bufC[NNODES * HDIM];
__device__ float g_invs[NNODES];
__device__ float g_pooled[NGRAPH * HDIM];

// ---------------- degree / normalization ----------------
__global__ void k_fill1(float* v, int n) {
    int i = blockIdx.x * blockDim.x + threadIdx.x;
    if (i < n) v[i] = 1.0f;   // self-loop contributes 1 to every degree
}

__global__ void k_degcount(const int* __restrict__ dst, float* deg, int E) {
    int e = blockIdx.x * blockDim.x + threadIdx.x;
    if (e < E) atomicAdd(&deg[dst[e]], 1.0f);
}

__global__ void k_rsqrt(float* v, int n) {
    int i = blockIdx.x * blockDim.x + threadIdx.x;
    if (i < n) v[i] = rsqrtf(v[i]);
}

// ---------------- GEMM: C[M,128] = (reluA? relu(A) : A)[M,128] @ W[128,128] + bias ----------------
__global__ void gemm_nn(const float* __restrict__ A, const float* __restrict__ W,
                        const float* __restrict__ bias, float* __restrict__ C,
                        int M, int reluA)
{
    extern __shared__ float sm[];
    float* Wsm = sm;               // 128*128 floats
    float* Asm = sm + 128 * 128;   // MTILE*128 floats
    const int tid = threadIdx.x;

    // load W (16384 floats) — 16 float4 per thread, coalesced
    #pragma unroll
    for (int i = tid * 4; i < 128 * 128; i += 256 * 4) {
        *(float4*)(Wsm + i) = *(const float4*)(W + i);
    }

    const int row0 = blockIdx.x * MTILE;
    // load A tile (MTILE x 128) — 8 float4 per thread
    #pragma unroll
    for (int i = tid * 4; i < MTILE * 128; i += 256 * 4) {
        int r = i >> 7;
        int c = i & 127;
        int gr = row0 + r;
        float4 v = make_float4(0.f, 0.f, 0.f, 0.f);
        if (gr < M) v = *(const float4*)(A + (size_t)gr * 128 + c);
        if (reluA) {
            v.x = fmaxf(v.x, 0.f); v.y = fmaxf(v.y, 0.f);
            v.z = fmaxf(v.z, 0.f); v.w = fmaxf(v.w, 0.f);
        }
        *(float4*)(Asm + i) = v;
    }
    __syncthreads();

    const int tx = tid & 31;   // column group: cols [tx*4, tx*4+4)
    const int ty = tid >> 5;   // row group: rows [ty*8, ty*8+8)

    float acc[8][4];
    #pragma unroll
    for (int r = 0; r < 8; ++r)
        #pragma unroll
        for (int c = 0; c < 4; ++c) acc[r][c] = 0.f;

    const float4* Wv = (const float4*)Wsm;   // row k -> Wv[k*32 + tx]

    #pragma unroll 4
    for (int k4 = 0; k4 < 32; ++k4) {
        float4 w0 = Wv[(k4 * 4 + 0) * 32 + tx];
        float4 w1 = Wv[(k4 * 4 + 1) * 32 + tx];
        float4 w2 = Wv[(k4 * 4 + 2) * 32 + tx];
        float4 w3 = Wv[(k4 * 4 + 3) * 32 + tx];
        #pragma unroll
        for (int r = 0; r < 8; ++r) {
            float4 a = *(const float4*)(Asm + (ty * 8 + r) * 128 + k4 * 4);
            acc[r][0] = fmaf(a.x, w0.x, acc[r][0]);
            acc[r][0] = fmaf(a.y, w1.x, acc[r][0]);
            acc[r][0] = fmaf(a.z, w2.x, acc[r][0]);
            acc[r][0] = fmaf(a.w, w3.x, acc[r][0]);
            acc[r][1] = fmaf(a.x, w0.y, acc[r][1]);
            acc[r][1] = fmaf(a.y, w1.y, acc[r][1]);
            acc[r][1] = fmaf(a.z, w2.y, acc[r][1]);
            acc[r][1] = fmaf(a.w, w3.y, acc[r][1]);
            acc[r][2] = fmaf(a.x, w0.z, acc[r][2]);
            acc[r][2] = fmaf(a.y, w1.z, acc[r][2]);
            acc[r][2] = fmaf(a.z, w2.z, acc[r][2]);
            acc[r][2] = fmaf(a.w, w3.z, acc[r][2]);
            acc[r][3] = fmaf(a.x, w0.w, acc[r][3]);
            acc[r][3] = fmaf(a.y, w1.w, acc[r][3]);
            acc[r][3] = fmaf(a.z, w2.w, acc[r][3]);
            acc[r][3] = fmaf(a.w, w3.w, acc[r][3]);
        }
    }

    float4 b = *(const float4*)(bias + tx * 4);
    const int gr0 = row0 + ty * 8;
    #pragma unroll
    for (int r = 0; r < 8; ++r) {
        int gr = gr0 + r;
        if (gr < M) {
            float4 o;
            o.x = acc[r][0] + b.x;
            o.y = acc[r][1] + b.y;
            o.z = acc[r][2] + b.z;
            o.w = acc[r][3] + b.w;
            *(float4*)(C + (size_t)gr * 128 + tx * 4) = o;
        }
    }
}

// ---------------- self-loop term: hnext[i,:] = hw[i,:] / deg[i] ----------------
__global__ void k_selfloop(const float* __restrict__ hw, const float* __restrict__ invs,
                           float* __restrict__ hnext, int N)
{
    int t = blockIdx.x * blockDim.x + threadIdx.x;   // one per float4
    if (t >= N * 32) return;
    int node = t >> 5;
    float c = invs[node];
    c *= c;
    float4 v = *(const float4*)(hw + (size_t)t * 4);
    float4 o = make_float4(v.x * c, v.y * c, v.z * c, v.w * c);
    *(float4*)(hnext + (size_t)t * 4) = o;
}

// ---------------- edge scatter: hnext[dst,:] += hw[src,:] * invs[src]*invs[dst] ----------------
__global__ void k_edge_scatter(const int* __restrict__ esrc, const int* __restrict__ edst,
                               const float* __restrict__ invs, const float* __restrict__ hw,
                               float* __restrict__ hnext, int E)
{
    int w = (blockIdx.x * blockDim.x + threadIdx.x) >> 5;
    if (w >= E) return;
    int lane = threadIdx.x & 31;
    int s = __ldg(esrc + w);
    int d = __ldg(edst + w);
    float c = __ldg(invs + s) * __ldg(invs + d);
    float4 v = *(const float4*)(hw + (size_t)s * 128 + lane * 4);
    float* p = hnext + (size_t)d * 128 + lane * 4;
    asm volatile("red.global.add.v4.f32 [%0], {%1,%2,%3,%4};"
                 :: "l"(p), "f"(v.x * c), "f"(v.y * c), "f"(v.z * c), "f"(v.w * c)
                 : "memory");
}

// ---------------- pooling ----------------
__global__ void k_zero(float* v, int n) {
    int i = blockIdx.x * blockDim.x + threadIdx.x;
    if (i < n) v[i] = 0.f;
}

__global__ void k_pool(const float* __restrict__ h, const int* __restrict__ batch,
                       float* __restrict__ pooled, int N)
{
    int w = (blockIdx.x * blockDim.x + threadIdx.x) >> 5;
    if (w >= N) return;
    int lane = threadIdx.x & 31;
    int g = __ldg(batch + w);
    float4 v = *(const float4*)(h + (size_t)w * 128 + lane * 4);
    float* p = pooled + (size_t)g * 128 + lane * 4;
    asm volatile("red.global.add.v4.f32 [%0], {%1,%2,%3,%4};"
                 :: "l"(p), "f"(v.x), "f"(v.y), "f"(v.z), "f"(v.w)
                 : "memory");
}

// ---------------- decoder: out[g,:10] = relu(pooled[g,:] @ w1 + b1) @ w2 + b2 ----------------
__global__ void k_decoder(const float* __restrict__ pooled,
                          const float* __restrict__ w1, const float* __restrict__ b1,
                          const float* __restrict__ w2, const float* __restrict__ b2,
                          float* __restrict__ out)
{
    __shared__ float p[128];
    __shared__ float d1[128];
    int g = blockIdx.x;
    int t = threadIdx.x;
    p[t] = pooled[g * 128 + t];
    __syncthreads();
    float s = b1[t];
    #pragma unroll 8
    for (int k = 0; k < 128; ++k) s = fmaf(p[k], w1[k * 128 + t], s);
    d1[t] = fmaxf(s, 0.f);
    __syncthreads();
    if (t < 10) {
        float s2 = b2[t];
        #pragma unroll 8
        for (int j = 0; j < 128; ++j) s2 = fmaf(d1[j], w2[j * 10 + t], s2);
        out[g * 10 + t] = s2;
    }
}

// ---------------- driver ----------------
extern "C" void kernel_launch(void* const* d_in, const int* in_sizes, int n_in,
                              void* d_out, int out_size)
{
    const float* x      = (const float*)d_in[0];
    const int*   ei     = (const int*)d_in[1];
    // d_in[2] = control_edge_index (unused by reference)
    const int*   batch  = (const int*)d_in[3];
    const float* enc_w1 = (const float*)d_in[4];
    const float* enc_b1 = (const float*)d_in[5];
    const float* enc_w2 = (const float*)d_in[6];
    const float* enc_b2 = (const float*)d_in[7];
    const float* conv_w = (const float*)d_in[8];
    const float* conv_b = (const float*)d_in[9];
    const float* dec_w1 = (const float*)d_in[10];
    const float* dec_b1 = (const float*)d_in[11];
    const float* dec_w2 = (const float*)d_in[12];
    const float* dec_b2 = (const float*)d_in[13];

    const int N = in_sizes[0] / HDIM;
    const int E = in_sizes[1] / 2;
    const int G = out_size / 10;

    float *bufA, *bufB, *bufC, *invs, *pooled;
    cudaGetSymbolAddress((void**)&bufA, g_bufA);
    cudaGetSymbolAddress((void**)&bufB, g_bufB);
    cudaGetSymbolAddress((void**)&bufC, g_bufC);
    cudaGetSymbolAddress((void**)&invs, g_invs);
    cudaGetSymbolAddress((void**)&pooled, g_pooled);

    const int* esrc = ei;
    const int* edst = ei + E;

    // degree -> inv sqrt (with self-loops)
    k_fill1<<<(N + 255) / 256, 256>>>(invs, N);
    k_degcount<<<(E + 255) / 256, 256>>>(edst, invs, E);
    k_rsqrt<<<(N + 255) / 256, 256>>>(invs, N);

    // GEMM config
    const int gblocks = (N + MTILE - 1) / MTILE;
    const size_t smem = (128 * 128 + MTILE * 128) * sizeof(float);
    cudaFuncSetAttribute(gemm_nn, cudaFuncAttributeMaxDynamicSharedMemorySize, (int)smem);

    // encoder: h = relu(x@w1+b1)@w2+b2
    gemm_nn<<<gblocks, 256, smem>>>(x, enc_w1, enc_b1, bufC, N, 0);
    gemm_nn<<<gblocks, 256, smem>>>(bufC, enc_w2, enc_b2, bufA, N, 1);

    float* hcur  = bufA;
    float* hnext = bufC;
    float* hw    = bufB;

    for (int l = 0; l < 3; ++l) {
        // hw = (l>0 ? relu(hcur) : hcur) @ conv_w[l] + conv_b[l]
        gemm_nn<<<gblocks, 256, smem>>>(hcur, conv_w + (size_t)l * 128 * 128,
                                        conv_b + (size_t)l * 128, hw, N, l > 0 ? 1 : 0);
        // hnext = D^-1 self-loop term, then scatter-add edges
        k_selfloop<<<(N * 32 + 255) / 256, 256>>>(hw, invs, hnext, N);
        {
            long long threads = (long long)E * 32;
            int blocks = (int)((threads + 255) / 256);
            k_edge_scatter<<<blocks, 256>>>(esrc, edst, invs, hw, hnext, E);
        }
        float* t = hcur; hcur = hnext; hnext = t;
    }

    // global add pool
    k_zero<<<(G * 128 + 255) / 256, 256>>>(pooled, G * 128);
    k_pool<<<(N * 32 + 255) / 256, 256>>>(hcur, batch, pooled, N);

    // decoder
    k_decoder<<<G, 128>>>(pooled, dec_w1, dec_b1, dec_w2, dec_b2, (float*)d_out);
}